// round 1
// baseline (speedup 1.0000x reference)
#include <cuda_runtime.h>

// ---------------- problem constants ----------------
namespace {
constexpr int Bn = 32;    // batch
constexpr int S  = 512;   // sequence
constexpr int H  = 768;   // hidden
constexpr int NN = 32;    // neighbors
constexpr int T  = 32;    // tokens per neighbor
constexpr int NE = 256;   // q/k embed
constexpr int AE = 128;   // attn embed
constexpr int RL = 8;     // region length (E1: 1..9, E2: 20..28)
constexpr float SCALE = 0.0625f;   // 1/sqrt(256)
constexpr float NEG   = 0.01f;     // leaky slope
}

// ---------------- scratch (device globals; no allocation) ----------------
__device__ float g_x    [Bn * S * H];          // updated x
__device__ float g_q    [Bn * S * NE];
__device__ float g_k    [Bn * S * NE];
__device__ float g_v    [Bn * S * H];
__device__ float g_probs[Bn * S * S];          // attention probs
__device__ float g_kn   [Bn * NN * T * NE];    // neighbor keys (reused per branch)
__device__ float g_msg1 [Bn * NN * RL * H];
__device__ float g_msg2 [Bn * NN * RL * H];
__device__ float g_qe1  [Bn * RL * NE];
__device__ float g_qe2  [Bn * RL * NE];
__device__ float g_att1 [Bn * NN];
__device__ float g_att2 [Bn * NN];
__device__ float g_u    [2 * H + 1];           // u1[0:H], u2[H:2H], cbase at [2H]

// ---------------- generic tiled SGEMM: C = alpha*(A @ opB) (+ bias) ----------------
// BM=BN=128, BK=8, 256 threads, 8x8 microtile. Requires M%128==0, N%128==0, K%8==0.
template<bool TRANSB, bool HASBIAS>
__global__ __launch_bounds__(256) void sgemm_k(
    const float* __restrict__ A, const float* __restrict__ Bm,
    const float* __restrict__ bias, float* __restrict__ C,
    int M, int N, int K, float alpha,
    long long sA, long long sB, long long sC)
{
    __shared__ float As[8][128];
    __shared__ float Bs[8][128];

    const int bz = blockIdx.z;
    A  += (long long)bz * sA;
    Bm += (long long)bz * sB;
    C  += (long long)bz * sC;

    const int m0 = blockIdx.y * 128;
    const int n0 = blockIdx.x * 128;
    const int tid = threadIdx.x;
    const int ty = tid >> 4, tx = tid & 15;

    float acc[8][8];
#pragma unroll
    for (int i = 0; i < 8; i++)
#pragma unroll
        for (int j = 0; j < 8; j++) acc[i][j] = 0.f;

    for (int k0 = 0; k0 < K; k0 += 8) {
        // A tile: 128 rows x 8 k, stored transposed As[k][m]
        {
            int row = tid >> 1, kq = (tid & 1) * 4;
            float4 av = *(const float4*)&A[(long long)(m0 + row) * K + k0 + kq];
            As[kq + 0][row] = av.x; As[kq + 1][row] = av.y;
            As[kq + 2][row] = av.z; As[kq + 3][row] = av.w;
        }
        if (!TRANSB) {
            int kk = tid >> 5, n4 = (tid & 31) * 4;
            float4 bv = *(const float4*)&Bm[(long long)(k0 + kk) * N + n0 + n4];
            *(float4*)&Bs[kk][n4] = bv;
        } else {
            int nn = tid >> 1, kq = (tid & 1) * 4;
            float4 bv = *(const float4*)&Bm[(long long)(n0 + nn) * K + k0 + kq];
            Bs[kq + 0][nn] = bv.x; Bs[kq + 1][nn] = bv.y;
            Bs[kq + 2][nn] = bv.z; Bs[kq + 3][nn] = bv.w;
        }
        __syncthreads();

#pragma unroll
        for (int kk = 0; kk < 8; kk++) {
            float a[8], b[8];
            *(float4*)&a[0] = *(const float4*)&As[kk][ty * 4];
            *(float4*)&a[4] = *(const float4*)&As[kk][64 + ty * 4];
            *(float4*)&b[0] = *(const float4*)&Bs[kk][tx * 4];
            *(float4*)&b[4] = *(const float4*)&Bs[kk][64 + tx * 4];
#pragma unroll
            for (int i = 0; i < 8; i++)
#pragma unroll
                for (int j = 0; j < 8; j++) acc[i][j] += a[i] * b[j];
        }
        __syncthreads();
    }

#pragma unroll
    for (int ri = 0; ri < 2; ri++)
#pragma unroll
        for (int i = 0; i < 4; i++) {
            int m = m0 + ri * 64 + ty * 4 + i;
#pragma unroll
            for (int cj = 0; cj < 2; cj++) {
                int n = n0 + cj * 64 + tx * 4;
                float4 cv;
                cv.x = acc[ri * 4 + i][cj * 4 + 0] * alpha;
                cv.y = acc[ri * 4 + i][cj * 4 + 1] * alpha;
                cv.z = acc[ri * 4 + i][cj * 4 + 2] * alpha;
                cv.w = acc[ri * 4 + i][cj * 4 + 3] * alpha;
                if (HASBIAS) {
                    cv.x += bias[n + 0]; cv.y += bias[n + 1];
                    cv.z += bias[n + 2]; cv.w += bias[n + 3];
                }
                *(float4*)&C[(long long)m * N + n] = cv;
            }
        }
}

// ---------------- u = Wa @ Wattn halves; cbase = ba.(w1+w2) + battn ----------------
__global__ void u_kernel(const float* __restrict__ Wa, const float* __restrict__ Wattn,
                         const float* __restrict__ ba, const float* __restrict__ battn)
{
    if (blockIdx.x < 6) {
        int g = blockIdx.x * 256 + threadIdx.x;   // [0, 1536)
        int j = g / H, h = g - j * H;
        float acc = 0.f;
#pragma unroll 8
        for (int a = 0; a < AE; a++) acc += Wa[h * AE + a] * Wattn[j * AE + a];
        g_u[g] = acc;
    } else {
        __shared__ float red[256];
        int tid = threadIdx.x;
        float v = 0.f;
        if (tid < AE) v = ba[tid] * (Wattn[tid] + Wattn[AE + tid]);
        red[tid] = v; __syncthreads();
        for (int s2 = 128; s2 > 0; s2 >>= 1) {
            if (tid < s2) red[tid] += red[tid + s2];
            __syncthreads();
        }
        if (tid == 0) g_u[2 * H] = red[0] + battn[0];
    }
}

// ---------------- q_e = e_fea @ Wq + bq  (256 blocks = B*RL, 256 threads = NE) ----
__global__ __launch_bounds__(256) void qe_kernel(
    const float* __restrict__ xs, const float* __restrict__ Wq,
    const float* __restrict__ bq, float* __restrict__ qe, int E0)
{
    __shared__ float xr[H];
    int b = blockIdx.x >> 3, l = blockIdx.x & 7;
    int tid = threadIdx.x;
    const float* row = xs + ((long long)b * S + E0 + l) * H;
    for (int i = tid; i < H; i += 256) xr[i] = row[i];
    __syncthreads();
    float acc = bq[tid];
#pragma unroll 8
    for (int h = 0; h < H; h++) acc += xr[h] * Wq[h * NE + tid];
    qe[(long long)(b * RL + l) * NE + tid] = acc;
}

// ---------------- per-(b,n): scores -> softmax over T -> message ----------------
__global__ __launch_bounds__(256) void neigh_kernel(
    const float* __restrict__ qe, const float* __restrict__ emb,
    float* __restrict__ msg)
{
    __shared__ float qs[RL * NE];
    __shared__ float ks[T * (NE + 1)];
    __shared__ float aw[RL * T];
    int b = blockIdx.x / NN, n = blockIdx.x % NN;
    int tid = threadIdx.x;

    const float* qb = qe + (long long)b * RL * NE;
    for (int i = tid; i < RL * NE; i += 256) qs[i] = qb[i];
    const float* kb = g_kn + (long long)(b * NN + n) * T * NE;
    for (int i = tid; i < T * NE; i += 256) {
        int r = i / NE, c = i - r * NE;
        ks[r * (NE + 1) + c] = kb[i];
    }
    __syncthreads();

    // one thread per (l, t) score; warp w handles row l=w
    int l = tid >> 5, tt = tid & 31;
    float s = 0.f;
    const float* qrow = qs + l * NE;
    const float* krow = ks + tt * (NE + 1);
#pragma unroll 8
    for (int e = 0; e < NE; e++) s += qrow[e] * krow[e];
    s *= SCALE;
    float m = s;
#pragma unroll
    for (int o = 16; o > 0; o >>= 1) m = fmaxf(m, __shfl_xor_sync(0xffffffffu, m, o));
    float ex = __expf(s - m), sum = ex;
#pragma unroll
    for (int o = 16; o > 0; o >>= 1) sum += __shfl_xor_sync(0xffffffffu, sum, o);
    aw[l * T + tt] = ex / sum;
    __syncthreads();

    const float* eb = emb + (long long)(b * NN + n) * T * H;
    float* mb = msg + (long long)(b * NN + n) * RL * H;
    for (int idx = tid; idx < RL * H; idx += 256) {
        int l2 = idx / H, h = idx - l2 * H;
        float acc = 0.f;
#pragma unroll 8
        for (int t2 = 0; t2 < T; t2++) acc += aw[l2 * T + t2] * eb[(long long)t2 * H + h];
        mb[idx] = acc;
    }
}

// ---------------- gate attention per b (grid Bn) ----------------
__global__ __launch_bounds__(256) void region_attn_kernel(
    const float* __restrict__ xs, const float* __restrict__ msg,
    const float* __restrict__ dist, const float* __restrict__ wb,
    const float* __restrict__ bb, float* __restrict__ att, int E0)
{
    __shared__ float red[256];
    __shared__ float sc[NN];
    int b = blockIdx.x, tid = threadIdx.x;

    float p = 0.f;
    const float* xb = xs + ((long long)b * S + E0) * H;
    for (int i = tid; i < RL * H; i += 256) p += xb[i] * g_u[i % H];
    red[tid] = p; __syncthreads();
    for (int s2 = 128; s2 > 0; s2 >>= 1) {
        if (tid < s2) red[tid] += red[tid + s2];
        __syncthreads();
    }
    float feasdot = red[0] / (float)RL;
    __syncthreads();

    for (int n = 0; n < NN; n++) {
        const float* mb = msg + (long long)(b * NN + n) * RL * H;
        float p2 = 0.f;
        for (int i = tid; i < RL * H; i += 256) p2 += mb[i] * g_u[H + i % H];
        red[tid] = p2; __syncthreads();
        for (int s2 = 128; s2 > 0; s2 >>= 1) {
            if (tid < s2) red[tid] += red[tid + s2];
            __syncthreads();
        }
        if (tid == 0) {
            float pre = feasdot + red[0] / (float)RL + g_u[2 * H];
            float z = pre >= 0.f ? pre : NEG * pre;
            sc[n] = z + dist[b * NN + n] * wb[0] + bb[0];
        }
        __syncthreads();
    }

    if (tid < 32) {
        float v = sc[tid];
        float m = v;
#pragma unroll
        for (int o = 16; o > 0; o >>= 1) m = fmaxf(m, __shfl_xor_sync(0xffffffffu, m, o));
        float e = __expf(v - m), s = e;
#pragma unroll
        for (int o = 16; o > 0; o >>= 1) s += __shfl_xor_sync(0xffffffffu, s, o);
        att[b * NN + tid] = e / s;
    }
}

// ---------------- x = xs (+ region message aggregation) ----------------
__global__ void build_x_kernel(const float* __restrict__ xs)
{
    long long idx = (long long)blockIdx.x * 256 + threadIdx.x;
    float v = xs[idx];
    int h = (int)(idx % H);
    int s = (int)((idx / H) % S);
    int b = (int)(idx / ((long long)H * S));
    if (s >= 1 && s < 9) {
        int l = s - 1;
#pragma unroll 4
        for (int n = 0; n < NN; n++)
            v += g_att1[b * NN + n] * g_msg1[(((long long)(b * NN + n)) * RL + l) * H + h];
    } else if (s >= 20 && s < 28) {
        int l = s - 20;
#pragma unroll 4
        for (int n = 0; n < NN; n++)
            v += g_att2[b * NN + n] * g_msg2[(((long long)(b * NN + n)) * RL + l) * H + h];
    }
    g_x[idx] = v;
}

// ---------------- row softmax over 512 cols of g_probs ----------------
__global__ __launch_bounds__(256) void softmax_rows_kernel()
{
    __shared__ float red[256];
    long long row = blockIdx.x;
    float* r = g_probs + row * S;
    int tid = threadIdx.x;
    float a = r[tid], b2 = r[tid + 256];
    float m = fmaxf(a, b2);
    red[tid] = m; __syncthreads();
    for (int s2 = 128; s2 > 0; s2 >>= 1) {
        if (tid < s2) red[tid] = fmaxf(red[tid], red[tid + s2]);
        __syncthreads();
    }
    float M = red[0]; __syncthreads();
    float ea = __expf(a - M), eb = __expf(b2 - M);
    red[tid] = ea + eb; __syncthreads();
    for (int s2 = 128; s2 > 0; s2 >>= 1) {
        if (tid < s2) red[tid] += red[tid + s2];
        __syncthreads();
    }
    float inv = 1.f / red[0];
    r[tid] = ea * inv; r[tid + 256] = eb * inv;
}

// ---------------- launch ----------------
extern "C" void kernel_launch(void* const* d_in, const int* in_sizes, int n_in,
                              void* d_out, int out_size)
{
    const float* xs    = (const float*)d_in[0];
    const float* n1emb = (const float*)d_in[1];
    const float* n2emb = (const float*)d_in[2];
    const float* dist1 = (const float*)d_in[3];
    const float* dist2 = (const float*)d_in[4];
    const float* Wq    = (const float*)d_in[5];
    const float* bq    = (const float*)d_in[6];
    const float* Wk    = (const float*)d_in[7];
    const float* bk    = (const float*)d_in[8];
    const float* Wv    = (const float*)d_in[9];
    const float* bv    = (const float*)d_in[10];
    const float* Wa    = (const float*)d_in[11];
    const float* ba    = (const float*)d_in[12];
    const float* Wattn = (const float*)d_in[13];
    const float* battn = (const float*)d_in[14];
    const float* wb    = (const float*)d_in[15];
    const float* bb    = (const float*)d_in[16];
    float* out = (float*)d_out;

    float *px, *pq, *pk, *pv, *pp, *pkn, *pm1, *pm2, *pqe1, *pqe2, *pa1, *pa2;
    cudaGetSymbolAddress((void**)&px,   g_x);
    cudaGetSymbolAddress((void**)&pq,   g_q);
    cudaGetSymbolAddress((void**)&pk,   g_k);
    cudaGetSymbolAddress((void**)&pv,   g_v);
    cudaGetSymbolAddress((void**)&pp,   g_probs);
    cudaGetSymbolAddress((void**)&pkn,  g_kn);
    cudaGetSymbolAddress((void**)&pm1,  g_msg1);
    cudaGetSymbolAddress((void**)&pm2,  g_msg2);
    cudaGetSymbolAddress((void**)&pqe1, g_qe1);
    cudaGetSymbolAddress((void**)&pqe2, g_qe2);
    cudaGetSymbolAddress((void**)&pa1,  g_att1);
    cudaGetSymbolAddress((void**)&pa2,  g_att2);

    // gate projection vectors
    u_kernel<<<7, 256>>>(Wa, Wattn, ba, battn);

    // per-branch neighbor queries
    qe_kernel<<<Bn * RL, 256>>>(xs, Wq, bq, pqe1, 1);
    qe_kernel<<<Bn * RL, 256>>>(xs, Wq, bq, pqe2, 20);

    // branch 1: kn GEMM then fused attn+message
    dim3 gkn(NE / 128, (Bn * NN * T) / 128, 1);
    sgemm_k<false, true><<<gkn, 256>>>(n1emb, Wk, bk, pkn, Bn * NN * T, NE, H, 1.f, 0, 0, 0);
    neigh_kernel<<<Bn * NN, 256>>>(pqe1, n1emb, pm1);

    // branch 2 (reuses g_kn)
    sgemm_k<false, true><<<gkn, 256>>>(n2emb, Wk, bk, pkn, Bn * NN * T, NE, H, 1.f, 0, 0, 0);
    neigh_kernel<<<Bn * NN, 256>>>(pqe2, n2emb, pm2);

    // gate attention weights
    region_attn_kernel<<<Bn, 256>>>(xs, pm1, dist1, wb, bb, pa1, 1);
    region_attn_kernel<<<Bn, 256>>>(xs, pm2, dist2, wb, bb, pa2, 20);

    // x = xs + gated messages
    build_x_kernel<<<(Bn * S * H) / 256, 256>>>(xs);

    // final attention projections
    sgemm_k<false, true><<<dim3(NE / 128, (Bn * S) / 128, 1), 256>>>(
        px, Wq, bq, pq, Bn * S, NE, H, 1.f, 0, 0, 0);
    sgemm_k<false, true><<<dim3(NE / 128, (Bn * S) / 128, 1), 256>>>(
        px, Wk, bk, pk, Bn * S, NE, H, 1.f, 0, 0, 0);
    sgemm_k<false, true><<<dim3(H / 128, (Bn * S) / 128, 1), 256>>>(
        px, Wv, bv, pv, Bn * S, H, H, 1.f, 0, 0, 0);

    // scores = scale * q @ k^T  (batched, transB)
    sgemm_k<true, false><<<dim3(S / 128, S / 128, Bn), 256>>>(
        pq, pk, nullptr, pp, S, S, NE, SCALE,
        (long long)S * NE, (long long)S * NE, (long long)S * S);

    softmax_rows_kernel<<<Bn * S, 256>>>();

    // out = probs @ v (batched)
    sgemm_k<false, false><<<dim3(H / 128, S / 128, Bn), 256>>>(
        pp, pv, nullptr, out, S, H, S, 1.f,
        (long long)S * S, (long long)S * H, (long long)S * H);
}